// round 5
// baseline (speedup 1.0000x reference)
#include <cuda_runtime.h>
#include <cuda_bf16.h>

#define BATCH 16
#define N 256
#define DIM 128

// Scratch (device globals: allocation-free per harness rules)
__device__ float  g_dist[BATCH * N * N];   // 4 MB, fp32 pairwise distances
__device__ double g_bsum[BATCH];           // per-batch matched sums

// ---------------------------------------------------------------------------
// Kernel A: pairwise L2 distances. One block computes a 16x16 tile of dist.
// ---------------------------------------------------------------------------
__global__ __launch_bounds__(256) void dist_kernel(const float* __restrict__ pred,
                                                   const float* __restrict__ tgt) {
    __shared__ float sp[16 * 132];
    __shared__ float st[16 * 132];
    const int b  = blockIdx.z;
    const int rt = blockIdx.y;
    const int ct = blockIdx.x;
    const int tid = threadIdx.x;

    const float4* p4 = (const float4*)(pred + (size_t)(b * N + rt * 16) * DIM);
    const float4* t4 = (const float4*)(tgt  + (size_t)(b * N + ct * 16) * DIM);
    for (int idx = tid; idx < 512; idx += 256) {
        int r = idx >> 5, c = idx & 31;
        *(float4*)&sp[r * 132 + c * 4] = p4[idx];
        *(float4*)&st[r * 132 + c * 4] = t4[idx];
    }
    __syncthreads();

    const int ti = tid >> 4;
    const int tj = tid & 15;
    float acc = 0.f;
#pragma unroll
    for (int d4 = 0; d4 < 32; ++d4) {
        float4 a = *(const float4*)&sp[ti * 132 + d4 * 4];
        float4 c = *(const float4*)&st[tj * 132 + d4 * 4];
        float dx = a.x - c.x, dy = a.y - c.y, dz = a.z - c.z, dw = a.w - c.w;
        acc += dx * dx + dy * dy + dz * dz + dw * dw;
    }
    g_dist[((size_t)b << 16) + (size_t)(rt * 16 + ti) * N + (ct * 16 + tj)] = sqrtf(acc);
}

// ---------------------------------------------------------------------------
// Kernel B: per-batch Jonker-Volgenant LSA on u16-quantized costs.
//   Init: column reduction + greedy pre-assign.
//   ARR:  augmenting row reduction (min/second-min, dual update, chase),
//         ring-buffer work queue (live window provably <= 256 < 1024).
//   Then: warp-0 Dijkstra with (D<<9|j)-packed redux-min, sentinel-masked
//         frozen columns. Each lane owns 8 consecutive columns in registers.
// ---------------------------------------------------------------------------
#define QSCALE 2048.0f

// dynamic smem layout (bytes)
#define OFF_COST 0                       // u16[65536] = 131072
#define OFF_U    131072                  // int[257]   = 1028  -> 132100
#define OFF_P    132100                  // u16[257]   = 514   -> 132614
#define OFF_WAY  132624                  // u16[256]   = 512   -> 133136 (16-aligned)
#define OFF_RMIN 133136                  // u16[256]   = 512   -> 133648 (16-aligned)
#define OFF_ROWT 133648                  // u32[8]     = 32    -> 133680
#define OFF_SRED 133680                  // double[8]  = 64    -> 133744
#define OFF_FQ   133744                  // u16[1024]  = 2048  -> 135792 (ring)
#define SMEM_B   135792

#define ARR_CAP  3072
#define FQ_MASK  1023

extern __shared__ char s_raw[];

__global__ __launch_bounds__(256) void hungarian_kernel() {
    const int b   = blockIdx.x;
    const int tid = threadIdx.x;

    unsigned short* cost  = (unsigned short*)(s_raw + OFF_COST);
    int*            u_    = (int*)(s_raw + OFF_U);
    unsigned short* p_    = (unsigned short*)(s_raw + OFF_P);
    unsigned short* way0_ = (unsigned short*)(s_raw + OFF_WAY);
    unsigned short* srmin = (unsigned short*)(s_raw + OFF_RMIN);
    unsigned*       srowt = (unsigned*)(s_raw + OFF_ROWT);
    double*         sred  = (double*)(s_raw + OFF_SRED);
    unsigned short* fq    = (unsigned short*)(s_raw + OFF_FQ);

    // ---- Phase 1: quantize fp32 distances into shared u16, init duals ----
    const float4* dsrc = (const float4*)(g_dist + ((size_t)b << 16));
    for (int idx = tid; idx < (N * N) / 4; idx += 256) {
        float4 d = dsrc[idx];
        int q0 = __float2int_rn(d.x * QSCALE); q0 = q0 > 65535 ? 65535 : q0;
        int q1 = __float2int_rn(d.y * QSCALE); q1 = q1 > 65535 ? 65535 : q1;
        int q2 = __float2int_rn(d.z * QSCALE); q2 = q2 > 65535 ? 65535 : q2;
        int q3 = __float2int_rn(d.w * QSCALE); q3 = q3 > 65535 ? 65535 : q3;
        ((ushort4*)cost)[idx] = make_ushort4((unsigned short)q0, (unsigned short)q1,
                                             (unsigned short)q2, (unsigned short)q3);
    }
    for (int i = tid; i < N + 1; i += 256) { u_[i] = 0; p_[i] = 0; }
    __syncthreads();

    // ---- Phase 2: warp 0 runs the LSA ----
    if (tid < 32) {
        const unsigned FULL = 0xffffffffu;
        const int lane = tid;

        // Column reduction: v[j] = min_i cost[i][j], rmin[j] = first argmin row.
        unsigned vmin[8]; int rmin[8];
#pragma unroll
        for (int k = 0; k < 8; ++k) { vmin[k] = 0xFFFFFFFFu; rmin[k] = 0; }
        for (int r = 0; r < N; ++r) {
            uint4 cc = ((const uint4*)(cost + (r << 8)))[lane];
            unsigned wv[4] = {cc.x, cc.y, cc.z, cc.w};
#pragma unroll
            for (int k = 0; k < 8; ++k) {
                unsigned c = (wv[k >> 1] >> ((k & 1) * 16)) & 0xFFFFu;
                if (c < vmin[k]) { vmin[k] = c; rmin[k] = r; }
            }
        }
        {
            unsigned a0 = (unsigned)rmin[0] | ((unsigned)rmin[1] << 16);
            unsigned a1 = (unsigned)rmin[2] | ((unsigned)rmin[3] << 16);
            unsigned a2 = (unsigned)rmin[4] | ((unsigned)rmin[5] << 16);
            unsigned a3 = (unsigned)rmin[6] | ((unsigned)rmin[7] << 16);
            ((uint4*)srmin)[lane] = make_uint4(a0, a1, a2, a3);
        }
        if (lane < 8) srowt[lane] = 0u;
        __syncwarp();
        // Greedy pre-assignment: column j -> rmin[j] if that row is still free.
        if (lane == 0) {
            for (int j = 0; j < N; ++j) {
                int r = srmin[j];
                unsigned wd = srowt[r >> 5];
                if (!((wd >> (r & 31)) & 1u)) {
                    srowt[r >> 5] = wd | (1u << (r & 31));
                    p_[j + 1] = (unsigned short)(r + 1);
                }
            }
        }
        __syncwarp();

        int vreg[8];
#pragma unroll
        for (int k = 0; k < 8; ++k) vreg[k] = (int)vmin[k];
        unsigned rt[8];
#pragma unroll
        for (int w = 0; w < 8; ++w) rt[w] = srowt[w];

        // ---- Augmenting row reduction (JV), ring-buffer queue ----
        {
            int t0 = 0;
            if (lane == 0) {
                for (int w = 0; w < 8; ++w) {
                    unsigned fb = ~rt[w];
                    while (fb) {
                        int bz = __ffs(fb) - 1; fb &= fb - 1;
                        fq[t0++] = (unsigned short)(w * 32 + bz);
                    }
                }
            }
            int tail = __shfl_sync(FULL, t0, 0);
            int head = 0, iter = 0;

            while (head < tail && iter < ARR_CAP) {
                int i = fq[head & FQ_MASK]; head++;   // broadcast LDS, uniform
                bool chase = true;
                while (chase && iter < ARR_CAP) {
                    iter++;
                    // row scan: two smallest packed (val<<9 | j)
                    uint4 cc = ((const uint4*)(cost + (i << 8)))[lane];
                    unsigned wv[4] = {cc.x, cc.y, cc.z, cc.w};
                    unsigned m1 = 0xFFFFFFFFu, m2 = 0xFFFFFFFFu;
#pragma unroll
                    for (int k = 0; k < 8; ++k) {
                        int c = (int)((wv[k >> 1] >> ((k & 1) * 16)) & 0xFFFFu);
                        int val = c - vreg[k];
                        if (val > 0x3FFFFF) val = 0x3FFFFF;   // pack safety
                        unsigned pk = (((unsigned)val) << 9) | (unsigned)((lane << 3) + k);
                        if (pk < m1) { m2 = m1; m1 = pk; }
                        else if (pk < m2) m2 = pk;
                    }
                    const unsigned g1 = __reduce_min_sync(FULL, m1);
                    const unsigned c2 = (m1 == g1) ? m2 : m1;
                    const unsigned g2 = __reduce_min_sync(FULL, c2);
                    int j1 = (int)(g1 & 511u);
                    const int mv1 = (int)(g1 >> 9);
                    const int mv2 = (int)(g2 >> 9);
                    int pj1 = p_[j1 + 1];          // broadcast LDS
                    if (mv1 < mv2) {
#pragma unroll
                        for (int k = 0; k < 8; ++k)
                            if (((lane << 3) + k) == j1) vreg[k] -= (mv2 - mv1);
                    } else if (pj1 != 0) {
                        // tie: prefer a free second-best column
                        int j2 = (int)(g2 & 511u);
                        int pj2 = p_[j2 + 1];
                        if (pj2 == 0) { j1 = j2; pj1 = 0; }
                    }
                    if (lane == 0) {
                        p_[j1 + 1] = (unsigned short)(i + 1);
                        u_[i + 1]  = mv2;
                    }
                    __syncwarp();
                    if (pj1 != 0) {
                        int disp = pj1 - 1;
                        if (mv1 < mv2) {
                            i = disp;              // immediate chase
                        } else {
                            if (lane == 0) fq[tail & FQ_MASK] = (unsigned short)disp;
                            tail++;
                            chase = false;
                        }
                    } else chase = false;
                }
            }
            __syncwarp();
            // Rebuild assigned-row bitmask from p_ (authoritative).
            unsigned rowbits[8];
#pragma unroll
            for (int w = 0; w < 8; ++w) rowbits[w] = 0u;
#pragma unroll
            for (int k = 0; k < 8; ++k) {
                int r = p_[(lane << 3) + k + 1];
                if (r) {
                    int rb = r - 1;
#pragma unroll
                    for (int w = 0; w < 8; ++w)
                        if ((rb >> 5) == w) rowbits[w] |= (1u << (rb & 31));
                }
            }
#pragma unroll
            for (int w = 0; w < 8; ++w) rt[w] = __reduce_or_sync(FULL, rowbits[w]);
        }

        // ---- Dijkstra for each remaining unassigned row ----
        for (int w = 0; w < 8; ++w) {
            unsigned freeb = ~rt[w];
            while (freeb) {
                const int bz = __ffs(freeb) - 1;
                freeb &= freeb - 1;
                const int i = w * 32 + bz + 1;

                unsigned Dp[8], offk[8], fz = 0;
                int wayreg[8], wlock[8], Sfz[8], pifz[8];
#pragma unroll
                for (int k = 0; k < 8; ++k) {
                    Dp[k] = 0xFFFFFFFFu;
                    wayreg[k] = 0;
                    offk[k] = (unsigned)((lane << 3) + k + 1) - (((unsigned)vreg[k]) << 9);
                }
                if (lane == 0) p_[0] = (unsigned short)i;

                int S = 0, i0 = i, j0 = 0, jfinal;

                while (true) {
                    const int u0 = u_[i0];
                    const uint4 cc = ((const uint4*)(cost + ((i0 - 1) << 8)))[lane];
                    const unsigned bsh = ((unsigned)(S - u0)) << 9;  // mod-2^32 ok
                    unsigned wv[4] = {cc.x, cc.y, cc.z, cc.w};
#pragma unroll
                    for (int k = 0; k < 8; ++k) {
                        unsigned word = wv[k >> 1];
                        unsigned csh = (k & 1) ? ((word >> 7) & 0x01FFFE00u)
                                               : ((word << 9) & 0x01FFFE00u);
                        unsigned cand = bsh + csh + offk[k];      // (D<<9)|j packed
                        if (cand < Dp[k]) { Dp[k] = cand; wayreg[k] = j0; }
                    }
                    unsigned m01 = Dp[0] < Dp[1] ? Dp[0] : Dp[1];
                    unsigned m23 = Dp[2] < Dp[3] ? Dp[2] : Dp[3];
                    unsigned m45 = Dp[4] < Dp[5] ? Dp[4] : Dp[5];
                    unsigned m67 = Dp[6] < Dp[7] ? Dp[6] : Dp[7];
                    unsigned ma = m01 < m23 ? m01 : m23;
                    unsigned mb = m45 < m67 ? m45 : m67;
                    const unsigned g = __reduce_min_sync(FULL, ma < mb ? ma : mb);
                    const int j1 = (int)(g & 511u);
                    S = (int)(g >> 9);
                    const int pj1 = p_[j1];
                    if (pj1 == 0) { jfinal = j1; break; }
#pragma unroll
                    for (int k = 0; k < 8; ++k)
                        if (((lane << 3) + k + 1) == j1) {
                            fz |= (1u << k);
                            Sfz[k] = S; pifz[k] = pj1;
                            wlock[k] = wayreg[k];          // snapshot predecessor
                            offk[k] += 0x80000000u;        // sentinel: never wins
                            Dp[k] = 0xFFFFFFFFu;
                        }
                    i0 = pj1; j0 = j1;
                }

                const int mu = S;
                {
                    unsigned wout[8];
#pragma unroll
                    for (int k = 0; k < 8; ++k)
                        wout[k] = (unsigned)(((fz >> k) & 1u) ? wlock[k] : wayreg[k]) & 0xFFFFu;
                    unsigned a0 = wout[0] | (wout[1] << 16);
                    unsigned a1 = wout[2] | (wout[3] << 16);
                    unsigned a2 = wout[4] | (wout[5] << 16);
                    unsigned a3 = wout[6] | (wout[7] << 16);
                    ((uint4*)way0_)[lane] = make_uint4(a0, a1, a2, a3);
                }
                __syncwarp();
                if (lane == 0) {
                    int jj = jfinal;
                    while (jj != 0) {
                        int jp = way0_[jj - 1];
                        p_[jj] = p_[jp];
                        jj = jp;
                    }
                    u_[i] += mu;
                }
#pragma unroll
                for (int k = 0; k < 8; ++k)
                    if ((fz >> k) & 1u) {
                        int adj = mu - Sfz[k];
                        vreg[k] -= adj;
                        u_[pifz[k]] += adj;
                    }
                __syncwarp();
            }
        }
    }
    __syncthreads();

    // ---- Phase 3: gather matched fp32 distances, deterministic block sum ----
    {
        const int j   = tid + 1;
        const int row = p_[j];
        float val = g_dist[((size_t)b << 16) + (size_t)(row - 1) * N + (j - 1)];
        double d = (double)val;
#pragma unroll
        for (int off = 16; off > 0; off >>= 1)
            d += __shfl_down_sync(0xffffffffu, d, off);
        if ((tid & 31) == 0) sred[tid >> 5] = d;
        __syncthreads();
        if (tid == 0) {
            double t = 0.0;
#pragma unroll
            for (int w = 0; w < 8; ++w) t += sred[w];   // fixed order
            g_bsum[b] = t;
        }
    }
}

// ---------------------------------------------------------------------------
// Kernel C: deterministic final reduce + mean
// ---------------------------------------------------------------------------
__global__ void finalize_kernel(float* __restrict__ out) {
    double t = 0.0;
#pragma unroll
    for (int b = 0; b < BATCH; ++b) t += g_bsum[b];
    out[0] = (float)(t / (double)(BATCH * N));
}

// ---------------------------------------------------------------------------
extern "C" void kernel_launch(void* const* d_in, const int* in_sizes, int n_in,
                              void* d_out, int out_size) {
    const float* pred = (const float*)d_in[0];
    const float* tgt  = (const float*)d_in[1];
    float* out = (float*)d_out;

    cudaFuncSetAttribute(hungarian_kernel,
                         cudaFuncAttributeMaxDynamicSharedMemorySize, SMEM_B);

    dist_kernel<<<dim3(16, 16, 16), 256>>>(pred, tgt);
    hungarian_kernel<<<BATCH, 256, SMEM_B>>>();
    finalize_kernel<<<1, 1>>>(out);
}

// round 6
// speedup vs baseline: 1.0921x; 1.0921x over previous
#include <cuda_runtime.h>
#include <cuda_bf16.h>

#define BATCH 16
#define N 256
#define DIM 128

// Scratch (device globals: allocation-free per harness rules)
__device__ float          g_dist[BATCH * N * N];   // 4 MB fp32 distances
__device__ unsigned short g_cost[BATCH * N * N];   // 2 MB u16 quantized costs
__device__ double         g_bsum[BATCH];           // per-batch matched sums

#define QSCALE 512.0f
#define QMAX   16383          // 14-bit D field ceiling

// ---------------------------------------------------------------------------
// Kernel A: pairwise L2 distances + quantization. 16x16 tile per block.
// ---------------------------------------------------------------------------
__global__ __launch_bounds__(256) void dist_kernel(const float* __restrict__ pred,
                                                   const float* __restrict__ tgt) {
    __shared__ float sp[16 * 132];
    __shared__ float st[16 * 132];
    const int b  = blockIdx.z;
    const int rt = blockIdx.y;
    const int ct = blockIdx.x;
    const int tid = threadIdx.x;

    const float4* p4 = (const float4*)(pred + (size_t)(b * N + rt * 16) * DIM);
    const float4* t4 = (const float4*)(tgt  + (size_t)(b * N + ct * 16) * DIM);
    for (int idx = tid; idx < 512; idx += 256) {
        int r = idx >> 5, c = idx & 31;
        *(float4*)&sp[r * 132 + c * 4] = p4[idx];
        *(float4*)&st[r * 132 + c * 4] = t4[idx];
    }
    __syncthreads();

    const int ti = tid >> 4;
    const int tj = tid & 15;
    float acc = 0.f;
#pragma unroll
    for (int d4 = 0; d4 < 32; ++d4) {
        float4 a = *(const float4*)&sp[ti * 132 + d4 * 4];
        float4 c = *(const float4*)&st[tj * 132 + d4 * 4];
        float dx = a.x - c.x, dy = a.y - c.y, dz = a.z - c.z, dw = a.w - c.w;
        acc += dx * dx + dy * dy + dz * dz + dw * dw;
    }
    float dd = sqrtf(acc);
    size_t o = ((size_t)b << 16) + (size_t)(rt * 16 + ti) * N + (ct * 16 + tj);
    g_dist[o] = dd;
    int q = __float2int_rn(dd * QSCALE);
    g_cost[o] = (unsigned short)(q > QMAX ? QMAX : q);
}

// ---------------------------------------------------------------------------
// Kernel B: per-batch Jonker-Volgenant LSA on u16 costs in shared.
//   Column reduction + greedy pre-assign, then warp-0 Dijkstra with
//   (D<<17|p<<8|j)-packed redux-min: winner's matched row p falls out of
//   the redux result (no dependent p-load on the critical path). Frozen
//   columns carry bit31 in their pack constant and never win.
// ---------------------------------------------------------------------------
// dynamic smem layout (bytes)
#define OFF_COST 0                       // u16[65536] = 131072
#define OFF_U    131072                  // int[257]   = 1028  -> 132100
#define OFF_P    132100                  // u16[257]   = 514   -> 132614
#define OFF_WAY  132624                  // u16[256]   = 512   -> 133136 (16-aligned)
#define OFF_RMIN 133136                  // u16[256]   = 512   -> 133648 (16-aligned)
#define OFF_ROWT 133648                  // u32[8]     = 32    -> 133680
#define OFF_SRED 133680                  // double[8]  = 64    -> 133744
#define SMEM_B   133744

#define JROOT 0x1FF                      // way-chain root marker (9 bits)

extern __shared__ char s_raw[];

__global__ __launch_bounds__(256) void hungarian_kernel() {
    const int b   = blockIdx.x;
    const int tid = threadIdx.x;

    unsigned short* cost  = (unsigned short*)(s_raw + OFF_COST);
    int*            u_    = (int*)(s_raw + OFF_U);        // 1-based rows
    unsigned short* p_    = (unsigned short*)(s_raw + OFF_P);   // p_[j+1], 0 = free
    unsigned short* way0_ = (unsigned short*)(s_raw + OFF_WAY); // 0-based cols
    unsigned short* srmin = (unsigned short*)(s_raw + OFF_RMIN);
    unsigned*       srowt = (unsigned*)(s_raw + OFF_ROWT);
    double*         sred  = (double*)(s_raw + OFF_SRED);

    // ---- Phase 1: copy quantized costs into shared, init state ----
    const uint4* csrc = (const uint4*)(g_cost + ((size_t)b << 16));
    uint4* cdst = (uint4*)cost;
    for (int idx = tid; idx < (N * N) / 8; idx += 256) cdst[idx] = csrc[idx];
    for (int i = tid; i < N + 1; i += 256) { u_[i] = 0; p_[i] = 0; }
    __syncthreads();

    // ---- Phase 2: warp 0 runs the LSA ----
    if (tid < 32) {
        const unsigned FULL = 0xffffffffu;
        const int lane = tid;

        // Column reduction: v[j] = min_i cost[i][j], rmin[j] = first argmin row.
        unsigned vmin[8]; int rmin[8];
#pragma unroll
        for (int k = 0; k < 8; ++k) { vmin[k] = 0xFFFFFFFFu; rmin[k] = 0; }
        for (int r = 0; r < N; ++r) {
            uint4 cc = ((const uint4*)(cost + (r << 8)))[lane];
            unsigned wv[4] = {cc.x, cc.y, cc.z, cc.w};
#pragma unroll
            for (int k = 0; k < 8; ++k) {
                unsigned c = (wv[k >> 1] >> ((k & 1) * 16)) & 0xFFFFu;
                if (c < vmin[k]) { vmin[k] = c; rmin[k] = r; }
            }
        }
        {
            unsigned a0 = (unsigned)rmin[0] | ((unsigned)rmin[1] << 16);
            unsigned a1 = (unsigned)rmin[2] | ((unsigned)rmin[3] << 16);
            unsigned a2 = (unsigned)rmin[4] | ((unsigned)rmin[5] << 16);
            unsigned a3 = (unsigned)rmin[6] | ((unsigned)rmin[7] << 16);
            ((uint4*)srmin)[lane] = make_uint4(a0, a1, a2, a3);
        }
        if (lane < 8) srowt[lane] = 0u;
        __syncwarp();
        // Greedy pre-assignment: column j -> rmin[j] if that row is still free.
        if (lane == 0) {
            for (int j = 0; j < N; ++j) {
                int r = srmin[j];
                unsigned wd = srowt[r >> 5];
                if (!((wd >> (r & 31)) & 1u)) {
                    srowt[r >> 5] = wd | (1u << (r & 31));
                    p_[j + 1] = (unsigned short)(r + 1);
                }
            }
        }
        __syncwarp();

        int vreg[8];
#pragma unroll
        for (int k = 0; k < 8; ++k) vreg[k] = (int)vmin[k];
        unsigned rt[8];
#pragma unroll
        for (int w = 0; w < 8; ++w) rt[w] = srowt[w];

        // ---- Dijkstra for each unassigned row ----
        for (int w = 0; w < 8; ++w) {
            unsigned freeb = ~rt[w];
            while (freeb) {
                const int bz = __ffs(freeb) - 1;
                freeb &= freeb - 1;
                const int i = w * 32 + bz + 1;     // 1-based start row; u_[i]==0

                // per-column pack constants: (p<<8)|j, bit31 = frozen
                unsigned pkj[8], Dp[8], fz = 0;
                int wayreg[8], wlock[8], Sfz[8], pifz[8];
#pragma unroll
                for (int k = 0; k < 8; ++k) {
                    int j = (lane << 3) + k;
                    pkj[k] = ((unsigned)p_[j + 1] << 8) | (unsigned)j;
                    Dp[k] = 0xFFFFFFFFu;
                    wayreg[k] = JROOT;
                }

                int S = 0, i0 = i, u0 = 0, j0 = JROOT, jfinal;

                while (true) {
                    const uint4 cc = ((const uint4*)(cost + ((i0 - 1) << 8)))[lane];
                    const int baseS = S - u0;
                    unsigned wv[4] = {cc.x, cc.y, cc.z, cc.w};
#pragma unroll
                    for (int k = 0; k < 8; ++k) {
                        int c = (int)((wv[k >> 1] >> ((k & 1) * 16)) & 0xFFFFu);
                        int d = baseS + c - vreg[k];       // >= S >= 0 (feasible duals)
                        d = d > QMAX ? QMAX : d;           // winners never clamped
                        unsigned cand = (((unsigned)d) << 17) | pkj[k];
                        if (cand < Dp[k]) { Dp[k] = cand; wayreg[k] = j0; }
                    }
                    unsigned m01 = Dp[0] < Dp[1] ? Dp[0] : Dp[1];
                    unsigned m23 = Dp[2] < Dp[3] ? Dp[2] : Dp[3];
                    unsigned m45 = Dp[4] < Dp[5] ? Dp[4] : Dp[5];
                    unsigned m67 = Dp[6] < Dp[7] ? Dp[6] : Dp[7];
                    unsigned ma = m01 < m23 ? m01 : m23;
                    unsigned mb = m45 < m67 ? m45 : m67;
                    const unsigned g = __reduce_min_sync(FULL, ma < mb ? ma : mb);

                    const int j1  = (int)(g & 0xFFu);
                    const int pj1 = (int)((g >> 8) & 0x1FFu);
                    S = (int)(g >> 17);
                    if (pj1 == 0) { jfinal = j1; break; }
#pragma unroll
                    for (int k = 0; k < 8; ++k)
                        if (((lane << 3) + k) == j1) {
                            fz |= (1u << k);
                            Sfz[k] = S; pifz[k] = pj1;
                            wlock[k] = wayreg[k];          // snapshot predecessor
                            pkj[k] |= 0x80000000u;         // frozen: never wins
                            Dp[k] = 0xFFFFFFFFu;
                        }
                    i0 = pj1;
                    u0 = u_[i0];                           // overlaps next cost load
                    j0 = j1;
                }

                const int mu = S;
                // publish way pointers (frozen columns use freeze-time snapshot)
                {
                    unsigned wout[8];
#pragma unroll
                    for (int k = 0; k < 8; ++k)
                        wout[k] = (unsigned)(((fz >> k) & 1u) ? wlock[k] : wayreg[k]) & 0xFFFFu;
                    unsigned a0 = wout[0] | (wout[1] << 16);
                    unsigned a1 = wout[2] | (wout[3] << 16);
                    unsigned a2 = wout[4] | (wout[5] << 16);
                    unsigned a3 = wout[6] | (wout[7] << 16);
                    ((uint4*)way0_)[lane] = make_uint4(a0, a1, a2, a3);
                }
                __syncwarp();
                if (lane == 0) {
                    int cur = jfinal;                      // augment along path
                    while (true) {
                        int pr = way0_[cur];
                        if (pr == JROOT) { p_[cur + 1] = (unsigned short)i; break; }
                        p_[cur + 1] = p_[pr + 1];
                        cur = pr;
                    }
                    u_[i] += mu;
                }
                // deferred dual updates (distinct rows per frozen column)
#pragma unroll
                for (int k = 0; k < 8; ++k)
                    if ((fz >> k) & 1u) {
                        int adj = mu - Sfz[k];
                        vreg[k] -= adj;
                        u_[pifz[k]] += adj;
                    }
                __syncwarp();
            }
        }
    }
    __syncthreads();

    // ---- Phase 3: gather matched fp32 distances, deterministic block sum ----
    {
        const int j   = tid + 1;
        const int row = p_[j];
        float val = g_dist[((size_t)b << 16) + (size_t)(row - 1) * N + (j - 1)];
        double d = (double)val;
#pragma unroll
        for (int off = 16; off > 0; off >>= 1)
            d += __shfl_down_sync(0xffffffffu, d, off);
        if ((tid & 31) == 0) sred[tid >> 5] = d;
        __syncthreads();
        if (tid == 0) {
            double t = 0.0;
#pragma unroll
            for (int w = 0; w < 8; ++w) t += sred[w];   // fixed order
            g_bsum[b] = t;
        }
    }
}

// ---------------------------------------------------------------------------
// Kernel C: deterministic final reduce + mean
// ---------------------------------------------------------------------------
__global__ void finalize_kernel(float* __restrict__ out) {
    double t = 0.0;
#pragma unroll
    for (int b = 0; b < BATCH; ++b) t += g_bsum[b];
    out[0] = (float)(t / (double)(BATCH * N));
}

// ---------------------------------------------------------------------------
extern "C" void kernel_launch(void* const* d_in, const int* in_sizes, int n_in,
                              void* d_out, int out_size) {
    const float* pred = (const float*)d_in[0];
    const float* tgt  = (const float*)d_in[1];
    float* out = (float*)d_out;

    cudaFuncSetAttribute(hungarian_kernel,
                         cudaFuncAttributeMaxDynamicSharedMemorySize, SMEM_B);

    dist_kernel<<<dim3(16, 16, 16), 256>>>(pred, tgt);
    hungarian_kernel<<<BATCH, 256, SMEM_B>>>();
    finalize_kernel<<<1, 1>>>(out);
}